// round 11
// baseline (speedup 1.0000x reference)
#include <cuda_runtime.h>
#include <cstdint>

// Dice over B=4 batches, C=5 classes, N = 64*256*256 = 4,194,304 voxels/batch.
// Single fused persistent kernel: packed lane-parallel histograms +
// last-block epilogue.
//
// Steady-state model (R3-R10): warm graph replays sit at the LTS byte-
// throughput cap (~6.7-6.9 TB/s): all 128 MiB of label reads traverse L2,
// hitting for target (pinned via evict_last.v8; 64 MiB stable, 96 was not)
// and missing to DRAM for pred (streamed evict-first via __ldcs).
// Grid = 148 SMs x 8 CTAs = 1184 blocks: exactly one wave, no quantization.
// This round: unroll the chunk loop by 2 with front-batched loads (6 loads
// in flight per thread) to squeeze the last latency exposure.
//
// Packed counters: 32-bit accs, five 6-bit fields (shift = label*6). Up to
// 56 elems/thread -> max field 56 <= 63: safe; warp reduce at 64-bit after
// widening to 12-bit fields (warp max 1792 < 4096).

#define NUM_CLASSES 5
#define BATCHES     4
#define N_PER_BATCH (64 * 256 * 256)          // 4,194,304 elements
#define CHUNKS_PER_BATCH (N_PER_BATCH / 8)    // 524,288 32-byte chunks
#define THREADS     256
#define WARPS       (THREADS / 32)
#define BLOCKS_X    296                        // 296*4 = 1184 = 148 SM * 8 CTA
#define TPB         (BLOCKS_X * THREADS)       // 75,776 threads per batch
#define TOTAL_BLOCKS (BLOCKS_X * BATCHES)

// Zero at load; last block re-zeroes after use (deterministic across replays).
__device__ unsigned int g_counts[BATCHES * 15];
__device__ unsigned int g_done;

struct V8 { unsigned r[8]; };

__device__ __forceinline__ V8 ld_evict_last_v8(const void* p) {
    V8 v;
    asm volatile("ld.global.nc.L2::evict_last.v8.u32 "
                 "{%0,%1,%2,%3,%4,%5,%6,%7}, [%8];"
                 : "=r"(v.r[0]), "=r"(v.r[1]), "=r"(v.r[2]), "=r"(v.r[3]),
                   "=r"(v.r[4]), "=r"(v.r[5]), "=r"(v.r[6]), "=r"(v.r[7])
                 : "l"(p));
    return v;
}

__device__ __forceinline__ unsigned long long widen6to12(unsigned x) {
    // five 6-bit fields (at 0,6,12,18,24) -> five 12-bit fields (0,12,24,36,48)
    return (unsigned long long)(x & 63u)
         | ((unsigned long long)((x >> 6)  & 63u) << 12)
         | ((unsigned long long)((x >> 12) & 63u) << 24)
         | ((unsigned long long)((x >> 18) & 63u) << 36)
         | ((unsigned long long)((x >> 24) & 63u) << 48);
}

__global__ __launch_bounds__(THREADS, 8) void dice_fused_kernel(
    const char* __restrict__ pred, const char* __restrict__ tar,
    float* __restrict__ out)
{
    const unsigned batch = blockIdx.y;
    const unsigned idx   = blockIdx.x * THREADS + threadIdx.x;  // 0..75775
    const unsigned base8 = batch * (unsigned)CHUNKS_PER_BATCH;

    unsigned ap = 0u, at = 0u, ai = 0u;

    // Unrolled-by-2 grid-stride over this batch's 32-byte chunks.
    unsigned c8 = idx;
    for (; c8 + TPB < (unsigned)CHUNKS_PER_BATCH; c8 += 2u * TPB) {
        const size_t o0 = (size_t)(base8 + c8) * 32u;
        const size_t o1 = (size_t)(base8 + c8 + TPB) * 32u;
        // Front-batch all 6 loads.
        V8 t0 = ld_evict_last_v8(tar + o0);
        V8 t1 = ld_evict_last_v8(tar + o1);
        int4 p0a = __ldcs((const int4*)(pred + o0));
        int4 p0b = __ldcs((const int4*)(pred + o0) + 1);
        int4 p1a = __ldcs((const int4*)(pred + o1));
        int4 p1b = __ldcs((const int4*)(pred + o1) + 1);
        {
            int pe[8] = {p0a.x, p0a.y, p0a.z, p0a.w, p0b.x, p0b.y, p0b.z, p0b.w};
#pragma unroll
            for (int e = 0; e < 8; ++e) {
                int tv = (int)t0.r[e];
                unsigned opp = 1u << ((unsigned)pe[e] * 6u);
                ap += opp;
                at += 1u << ((unsigned)tv * 6u);
                if (pe[e] == tv) ai += opp;
            }
        }
        {
            int pe[8] = {p1a.x, p1a.y, p1a.z, p1a.w, p1b.x, p1b.y, p1b.z, p1b.w};
#pragma unroll
            for (int e = 0; e < 8; ++e) {
                int tv = (int)t1.r[e];
                unsigned opp = 1u << ((unsigned)pe[e] * 6u);
                ap += opp;
                at += 1u << ((unsigned)tv * 6u);
                if (pe[e] == tv) ai += opp;
            }
        }
    }
    // Tail: at most one remaining chunk.
    if (c8 < (unsigned)CHUNKS_PER_BATCH) {
        const size_t o0 = (size_t)(base8 + c8) * 32u;
        V8 t0 = ld_evict_last_v8(tar + o0);
        int4 p0a = __ldcs((const int4*)(pred + o0));
        int4 p0b = __ldcs((const int4*)(pred + o0) + 1);
        int pe[8] = {p0a.x, p0a.y, p0a.z, p0a.w, p0b.x, p0b.y, p0b.z, p0b.w};
#pragma unroll
        for (int e = 0; e < 8; ++e) {
            int tv = (int)t0.r[e];
            unsigned opp = 1u << ((unsigned)pe[e] * 6u);
            ap += opp;
            at += 1u << ((unsigned)tv * 6u);
            if (pe[e] == tv) ai += opp;
        }
    }

    // Widen (per-thread fields up to 56), warp reduce at 64-bit.
    unsigned long long acc_p = widen6to12(ap);
    unsigned long long acc_t = widen6to12(at);
    unsigned long long acc_i = widen6to12(ai);
#pragma unroll
    for (int o = 16; o > 0; o >>= 1) {
        acc_p += __shfl_down_sync(0xFFFFFFFFu, acc_p, o);
        acc_t += __shfl_down_sync(0xFFFFFFFFu, acc_t, o);
        acc_i += __shfl_down_sync(0xFFFFFFFFu, acc_i, o);
    }

    // Block reduce: per-warp private smem rows (no smem atomics, one barrier).
    __shared__ unsigned s[WARPS][15];
    __shared__ bool s_last;
    if ((threadIdx.x & 31u) == 0u) {
        const unsigned w = threadIdx.x >> 5;
#pragma unroll
        for (int c = 0; c < NUM_CLASSES; ++c) {
            s[w][c]      = (unsigned)((acc_p >> (12 * c)) & 0xFFFull);
            s[w][5 + c]  = (unsigned)((acc_t >> (12 * c)) & 0xFFFull);
            s[w][10 + c] = (unsigned)((acc_i >> (12 * c)) & 0xFFFull);
        }
    }
    __syncthreads();
    if (threadIdx.x < 15) {
        unsigned tot = 0u;
#pragma unroll
        for (int w = 0; w < WARPS; ++w) tot += s[w][threadIdx.x];
        atomicAdd(&g_counts[batch * 15 + threadIdx.x], tot);
    }

    // Last-block-done epilogue.
    if (threadIdx.x == 0) {
        __threadfence();  // order our g_counts atomics before the ticket
        unsigned ticket = atomicAdd(&g_done, 1u);
        s_last = (ticket == TOTAL_BLOCKS - 1u);
    }
    __syncthreads();
    if (s_last) {
        __threadfence();  // make all blocks' g_counts visible
        if (threadIdx.x < NUM_CLASSES) {
            const int c = threadIdx.x;
            float acc = 0.0f;
#pragma unroll
            for (int b = 0; b < BATCHES; ++b) {
                float ps = (float)g_counts[b * 15 + c];
                float ts = (float)g_counts[b * 15 + 5 + c];
                float is = (float)g_counts[b * 15 + 10 + c];
                float den = ps + ts;
                float num = 2.0f * is;
                if (den == 0.0f) { num = 1.0f; den = 1.0f; }
                acc += num / den;
            }
            out[c] = acc * (1.0f / (float)BATCHES);
        }
        __syncthreads();  // reads done before reset
        if (threadIdx.x < BATCHES * 15) g_counts[threadIdx.x] = 0u;
        if (threadIdx.x == 0) g_done = 0u;
    }
}

extern "C" void kernel_launch(void* const* d_in, const int* in_sizes, int n_in,
                              void* d_out, int out_size) {
    const char* pred = (const char*)d_in[0];
    const char* tar  = (const char*)d_in[1];
    float* out = (float*)d_out;

    dim3 grid(BLOCKS_X, BATCHES);
    dice_fused_kernel<<<grid, THREADS>>>(pred, tar, out);
}

// round 12
// speedup vs baseline: 1.0152x; 1.0152x over previous
#include <cuda_runtime.h>
#include <cstdint>

// Dice over B=4 batches, C=5 classes, N = 64*256*256 = 4,194,304 voxels/batch.
// Single fused persistent kernel: packed lane-parallel histograms +
// last-block epilogue.
//
// Converged steady-state model (R3-R11): warm graph replays sit on the LTS
// byte-throughput wall (~6.7 TB/s observed): all 128 MiB of label reads
// traverse L2 — target (64 MiB) hits via evict_last residency (64 MiB pinned
// is stable; 96 MiB was not, R7), pred (64 MiB) misses to DRAM, streamed
// evict-first. Occupancy (R8) and MLP (R11) levers were proven dead; only
// byte-path changes moved warm time. Floor ~18.6 us.
// Grid = 148 SMs x 8 CTAs = 1184 blocks: exactly one wave (R10, -3.4 us).
// This round: pred loads widened to v8 evict_first (halves pred load
// instructions / L1tex wavefronts; small bounded upside).
//
// Packed counters: 32-bit accs, five 6-bit fields (shift = label*6). Up to
// 56 elems/thread -> max field 56 <= 63: safe; warp reduce at 64-bit after
// widening to 12-bit fields (warp max 1792 < 4096).

#define NUM_CLASSES 5
#define BATCHES     4
#define N_PER_BATCH (64 * 256 * 256)          // 4,194,304 elements
#define CHUNKS_PER_BATCH (N_PER_BATCH / 8)    // 524,288 32-byte chunks
#define THREADS     256
#define WARPS       (THREADS / 32)
#define BLOCKS_X    296                        // 296*4 = 1184 = 148 SM * 8 CTA
#define TPB         (BLOCKS_X * THREADS)       // 75,776 threads per batch
#define TOTAL_BLOCKS (BLOCKS_X * BATCHES)

// Zero at load; last block re-zeroes after use (deterministic across replays).
__device__ unsigned int g_counts[BATCHES * 15];
__device__ unsigned int g_done;

struct V8 { unsigned r[8]; };

__device__ __forceinline__ V8 ld_evict_last_v8(const void* p) {
    V8 v;
    asm volatile("ld.global.nc.L2::evict_last.v8.u32 "
                 "{%0,%1,%2,%3,%4,%5,%6,%7}, [%8];"
                 : "=r"(v.r[0]), "=r"(v.r[1]), "=r"(v.r[2]), "=r"(v.r[3]),
                   "=r"(v.r[4]), "=r"(v.r[5]), "=r"(v.r[6]), "=r"(v.r[7])
                 : "l"(p));
    return v;
}

__device__ __forceinline__ V8 ld_evict_first_v8(const void* p) {
    V8 v;
    asm volatile("ld.global.nc.L2::evict_first.v8.u32 "
                 "{%0,%1,%2,%3,%4,%5,%6,%7}, [%8];"
                 : "=r"(v.r[0]), "=r"(v.r[1]), "=r"(v.r[2]), "=r"(v.r[3]),
                   "=r"(v.r[4]), "=r"(v.r[5]), "=r"(v.r[6]), "=r"(v.r[7])
                 : "l"(p));
    return v;
}

__device__ __forceinline__ unsigned long long widen6to12(unsigned x) {
    // five 6-bit fields (at 0,6,12,18,24) -> five 12-bit fields (0,12,24,36,48)
    return (unsigned long long)(x & 63u)
         | ((unsigned long long)((x >> 6)  & 63u) << 12)
         | ((unsigned long long)((x >> 12) & 63u) << 24)
         | ((unsigned long long)((x >> 18) & 63u) << 36)
         | ((unsigned long long)((x >> 24) & 63u) << 48);
}

__global__ __launch_bounds__(THREADS, 8) void dice_fused_kernel(
    const char* __restrict__ pred, const char* __restrict__ tar,
    float* __restrict__ out)
{
    const unsigned batch = blockIdx.y;
    const unsigned idx   = blockIdx.x * THREADS + threadIdx.x;  // 0..75775
    const unsigned base8 = batch * (unsigned)CHUNKS_PER_BATCH;

    unsigned ap = 0u, at = 0u, ai = 0u;

    // Unrolled-by-2 grid-stride over this batch's 32-byte chunks.
    unsigned c8 = idx;
    for (; c8 + TPB < (unsigned)CHUNKS_PER_BATCH; c8 += 2u * TPB) {
        const size_t o0 = (size_t)(base8 + c8) * 32u;
        const size_t o1 = (size_t)(base8 + c8 + TPB) * 32u;
        // Front-batch all 4 v8 loads (256 B in flight per thread).
        V8 t0 = ld_evict_last_v8(tar + o0);    // L2-resident
        V8 t1 = ld_evict_last_v8(tar + o1);
        V8 p0 = ld_evict_first_v8(pred + o0);  // streams from DRAM
        V8 p1 = ld_evict_first_v8(pred + o1);
#pragma unroll
        for (int e = 0; e < 8; ++e) {
            int pv = (int)p0.r[e], tv = (int)t0.r[e];
            unsigned opp = 1u << ((unsigned)pv * 6u);
            ap += opp;
            at += 1u << ((unsigned)tv * 6u);
            if (pv == tv) ai += opp;
        }
#pragma unroll
        for (int e = 0; e < 8; ++e) {
            int pv = (int)p1.r[e], tv = (int)t1.r[e];
            unsigned opp = 1u << ((unsigned)pv * 6u);
            ap += opp;
            at += 1u << ((unsigned)tv * 6u);
            if (pv == tv) ai += opp;
        }
    }
    // Tail: at most one remaining chunk.
    if (c8 < (unsigned)CHUNKS_PER_BATCH) {
        const size_t o0 = (size_t)(base8 + c8) * 32u;
        V8 t0 = ld_evict_last_v8(tar + o0);
        V8 p0 = ld_evict_first_v8(pred + o0);
#pragma unroll
        for (int e = 0; e < 8; ++e) {
            int pv = (int)p0.r[e], tv = (int)t0.r[e];
            unsigned opp = 1u << ((unsigned)pv * 6u);
            ap += opp;
            at += 1u << ((unsigned)tv * 6u);
            if (pv == tv) ai += opp;
        }
    }

    // Widen (per-thread fields up to 56), warp reduce at 64-bit.
    unsigned long long acc_p = widen6to12(ap);
    unsigned long long acc_t = widen6to12(at);
    unsigned long long acc_i = widen6to12(ai);
#pragma unroll
    for (int o = 16; o > 0; o >>= 1) {
        acc_p += __shfl_down_sync(0xFFFFFFFFu, acc_p, o);
        acc_t += __shfl_down_sync(0xFFFFFFFFu, acc_t, o);
        acc_i += __shfl_down_sync(0xFFFFFFFFu, acc_i, o);
    }

    // Block reduce: per-warp private smem rows (no smem atomics, one barrier).
    __shared__ unsigned s[WARPS][15];
    __shared__ bool s_last;
    if ((threadIdx.x & 31u) == 0u) {
        const unsigned w = threadIdx.x >> 5;
#pragma unroll
        for (int c = 0; c < NUM_CLASSES; ++c) {
            s[w][c]      = (unsigned)((acc_p >> (12 * c)) & 0xFFFull);
            s[w][5 + c]  = (unsigned)((acc_t >> (12 * c)) & 0xFFFull);
            s[w][10 + c] = (unsigned)((acc_i >> (12 * c)) & 0xFFFull);
        }
    }
    __syncthreads();
    if (threadIdx.x < 15) {
        unsigned tot = 0u;
#pragma unroll
        for (int w = 0; w < WARPS; ++w) tot += s[w][threadIdx.x];
        atomicAdd(&g_counts[batch * 15 + threadIdx.x], tot);
    }

    // Last-block-done epilogue.
    if (threadIdx.x == 0) {
        __threadfence();  // order our g_counts atomics before the ticket
        unsigned ticket = atomicAdd(&g_done, 1u);
        s_last = (ticket == TOTAL_BLOCKS - 1u);
    }
    __syncthreads();
    if (s_last) {
        __threadfence();  // make all blocks' g_counts visible
        if (threadIdx.x < NUM_CLASSES) {
            const int c = threadIdx.x;
            float acc = 0.0f;
#pragma unroll
            for (int b = 0; b < BATCHES; ++b) {
                float ps = (float)g_counts[b * 15 + c];
                float ts = (float)g_counts[b * 15 + 5 + c];
                float is = (float)g_counts[b * 15 + 10 + c];
                float den = ps + ts;
                float num = 2.0f * is;
                if (den == 0.0f) { num = 1.0f; den = 1.0f; }
                acc += num / den;
            }
            out[c] = acc * (1.0f / (float)BATCHES);
        }
        __syncthreads();  // reads done before reset
        if (threadIdx.x < BATCHES * 15) g_counts[threadIdx.x] = 0u;
        if (threadIdx.x == 0) g_done = 0u;
    }
}

extern "C" void kernel_launch(void* const* d_in, const int* in_sizes, int n_in,
                              void* d_out, int out_size) {
    const char* pred = (const char*)d_in[0];
    const char* tar  = (const char*)d_in[1];
    float* out = (float*)d_out;

    dim3 grid(BLOCKS_X, BATCHES);
    dice_fused_kernel<<<grid, THREADS>>>(pred, tar, out);
}